// round 8
// baseline (speedup 1.0000x reference)
#include <cuda_runtime.h>
#include <cuda_bf16.h>

// PositionalEncoding: out[pos,2i]=sin(pos*w_i), out[pos,2i+1]=cos(pos*w_i),
// w_i = 10000^{-i/512}, d_model=1024, seq_len = out_size/1024. X unused.
//
// R7: finer grid keeps helping (ramp/overlap-bound, all pipes idle).
// ROWS_PER_BLOCK=2, grid=4096, and direct evaluation — at 2 rows the
// rotation trick costs the same MUFU work as evaluating both rows
// directly, but adds serial depth. Per thread: 2 EX2 + 4 independent
// (Cody-Waite mod-2pi + __sincosf) + 2 STG.128.
// Floors: L2 store ~2.8us, STG.128 LSU issue ~2.9us, MUFU ~3us.

#define D_MODEL 1024
#define THREADS 256                    // thread t owns pair cols 2t, 2t+1
#define ROWS_PER_BLOCK 2
#define ROW_F4  (D_MODEL / 4)          // 256 float4 per row

#define NEG_K2    (-0.02595256324130752f)   // -log2(10000)/512
#define INV_2PI   (0.15915494309189535f)
#define TWO_PI_HI (6.28125f)                // exact in 9 mantissa bits
#define TWO_PI_LO (0.0019353071795864769f)  // 2pi - TWO_PI_HI

__device__ __forceinline__ void sincos_big(float theta, float* s, float* c) {
    // theta in [0, ~8200): 2-term Cody-Waite reduction mod 2pi, then MUFU.
    float n = rintf(theta * INV_2PI);
    float r = fmaf(-n, TWO_PI_HI, theta);
    r = fmaf(-n, TWO_PI_LO, r);
    __sincosf(r, s, c);
}

__global__ __launch_bounds__(THREADS, 8)
void pe_kernel(float4* __restrict__ out, int seq_len) {
    const int t = threadIdx.x;

    // Inverse frequencies (each via its own exp2f — accuracy-critical).
    const float w0 = exp2f((float)(2 * t)     * NEG_K2);
    const float w1 = exp2f((float)(2 * t + 1) * NEG_K2);

    const int row0 = blockIdx.x * ROWS_PER_BLOCK;
    if (row0 >= seq_len) return;

    const float p0 = (float)row0;
    const float p1 = (float)(row0 + 1);

    // Four independent sincos evaluations -> MUFU pipeline overlap.
    float sa, ca, sb, cb, sc, cc, sd, cd;
    sincos_big(p0 * w0, &sa, &ca);
    sincos_big(p0 * w1, &sb, &cb);
    sincos_big(p1 * w0, &sc, &cc);
    sincos_big(p1 * w1, &sd, &cd);

    float4* p = out + (size_t)row0 * ROW_F4 + t;
    p[0] = make_float4(sa, ca, sb, cb);
    if (row0 + 1 < seq_len)
        p[ROW_F4] = make_float4(sc, cc, sd, cd);
}

extern "C" void kernel_launch(void* const* d_in, const int* in_sizes, int n_in,
                              void* d_out, int out_size) {
    (void)d_in; (void)in_sizes; (void)n_in;
    const int seq_len = out_size / D_MODEL;    // 8192
    float4* out = (float4*)d_out;

    const int grid = (seq_len + ROWS_PER_BLOCK - 1) / ROWS_PER_BLOCK;  // 4096
    pe_kernel<<<grid, THREADS>>>(out, seq_len);
}

// round 9
// speedup vs baseline: 1.0519x; 1.0519x over previous
#include <cuda_runtime.h>
#include <cuda_bf16.h>
#include <cstdint>

// PositionalEncoding: out[pos,2i]=sin(pos*w_i), out[pos,2i+1]=cos(pos*w_i),
// w_i = 10000^{-i/512}, d_model=1024, seq_len = out_size/1024. X unused.
//
// R8 insight: every STG-based variant pins at dur ~= 2.8us / L2% (~7.4-8us),
// independent of compute => L2 *write* path via per-thread STG caps at
// ~2500 B/cyc. Test the bulk-store path: each block computes 4 contiguous
// rows (16KB) into SMEM (STS.128, conflict-free), then ONE cp.async.bulk
// shared->global pushes the chunk through the TMA/UBLKCP write engine.
// wait_group.read frees the CTA as soon as SMEM is re-readable, so store
// drain overlaps the next wave's compute.
// Compute = R7 best: dual rotation chains, Cody-Waite + MUFU seeds.

#define D_MODEL 1024
#define THREADS 256                    // thread t owns pair cols 2t, 2t+1
#define ROWS_PER_BLOCK 4
#define ROW_F4  (D_MODEL / 4)          // 256 float4 per row
#define CHUNK_BYTES (ROWS_PER_BLOCK * D_MODEL * 4)   // 16384

#define NEG_K2    (-0.02595256324130752f)   // -log2(10000)/512
#define INV_2PI   (0.15915494309189535f)
#define TWO_PI_HI (6.28125f)                // exact in 9 mantissa bits
#define TWO_PI_LO (0.0019353071795864769f)  // 2pi - TWO_PI_HI

__device__ __forceinline__ void sincos_big(float theta, float* s, float* c) {
    float n = rintf(theta * INV_2PI);
    float r = fmaf(-n, TWO_PI_HI, theta);
    r = fmaf(-n, TWO_PI_LO, r);
    __sincosf(r, s, c);
}

__device__ __forceinline__ uint32_t smem_u32(const void* p) {
    return (uint32_t)__cvta_generic_to_shared(p);
}

__global__ __launch_bounds__(THREADS, 8)
void pe_kernel(float4* __restrict__ out, int seq_len) {
    __shared__ float4 buf[ROWS_PER_BLOCK * THREADS];   // 16 KB, one 4-row chunk

    const int t = threadIdx.x;

    const float w0 = exp2f((float)(2 * t)     * NEG_K2);
    const float w1 = exp2f((float)(2 * t + 1) * NEG_K2);

    const int row0 = blockIdx.x * ROWS_PER_BLOCK;
    if (row0 >= seq_len) return;

    // Chain A seed: rows row0, row0+2 (fp32 angle product, like the ref).
    float sA0, cA0, sA1, cA1;
    sincos_big((float)row0 * w0, &sA0, &cA0);
    sincos_big((float)row0 * w1, &sA1, &cA1);

    float sw0, cw0, sw1, cw1;
    __sincosf(w0, &sw0, &cw0);
    __sincosf(w1, &sw1, &cw1);

    // Chain B = A rotated one row.
    float sB0 = fmaf(sA0, cw0,  cA0 * sw0);
    float cB0 = fmaf(cA0, cw0, -sA0 * sw0);
    float sB1 = fmaf(sA1, cw1,  cA1 * sw1);
    float cB1 = fmaf(cA1, cw1, -sA1 * sw1);

    // Double-angle 2-row step.
    const float s20 = 2.0f * sw0 * cw0;
    const float c20 = fmaf(-2.0f * sw0, sw0, 1.0f);
    const float s21 = 2.0f * sw1 * cw1;
    const float c21 = fmaf(-2.0f * sw1, sw1, 1.0f);

    if (row0 + ROWS_PER_BLOCK <= seq_len) {
        // rows 0,1 of the chunk
        buf[0 * THREADS + t] = make_float4(sA0, cA0, sA1, cA1);
        buf[1 * THREADS + t] = make_float4(sB0, cB0, sB1, cB1);
        // rotate both chains by 2 rows
        float nsA0 = fmaf(sA0, c20,  cA0 * s20);
        float ncA0 = fmaf(cA0, c20, -sA0 * s20);
        float nsA1 = fmaf(sA1, c21,  cA1 * s21);
        float ncA1 = fmaf(cA1, c21, -sA1 * s21);
        float nsB0 = fmaf(sB0, c20,  cB0 * s20);
        float ncB0 = fmaf(cB0, c20, -sB0 * s20);
        float nsB1 = fmaf(sB1, c21,  cB1 * s21);
        float ncB1 = fmaf(cB1, c21, -sB1 * s21);
        // rows 2,3
        buf[2 * THREADS + t] = make_float4(nsA0, ncA0, nsA1, ncA1);
        buf[3 * THREADS + t] = make_float4(nsB0, ncB0, nsB1, ncB1);

        __syncthreads();

        if (t == 0) {
            // Make generic-proxy STS visible to the async proxy, then one
            // 16KB bulk store of the contiguous chunk.
            asm volatile("fence.proxy.async.shared::cta;" ::: "memory");
            uint64_t dst = (uint64_t)(out + (size_t)row0 * ROW_F4);
            uint32_t src = smem_u32(buf);
            asm volatile(
                "cp.async.bulk.global.shared::cta.bulk_group [%0], [%1], %2;"
                :: "l"(dst), "r"(src), "r"((uint32_t)CHUNK_BYTES) : "memory");
            asm volatile("cp.async.bulk.commit_group;" ::: "memory");
            asm volatile("cp.async.bulk.wait_group.read 0;" ::: "memory");
        }
    } else {
        // Tail path (seq_len not divisible by 4): direct STG.
        float4* p = out + (size_t)row0 * ROW_F4 + t;
        const int rows = seq_len - row0;
        float as0 = sA0, ac0 = cA0, as1 = sA1, ac1 = cA1;
        float bs0 = sB0, bc0 = cB0, bs1 = sB1, bc1 = cB1;
        for (int r = 0; r < rows; r += 2) {
            p[0] = make_float4(as0, ac0, as1, ac1);
            if (r + 1 < rows) p[ROW_F4] = make_float4(bs0, bc0, bs1, bc1);
            p += 2 * ROW_F4;
            float nsA0 = fmaf(as0, c20,  ac0 * s20);
            float ncA0 = fmaf(ac0, c20, -as0 * s20);
            float nsA1 = fmaf(as1, c21,  ac1 * s21);
            float ncA1 = fmaf(ac1, c21, -as1 * s21);
            float nsB0 = fmaf(bs0, c20,  bc0 * s20);
            float ncB0 = fmaf(bc0, c20, -bs0 * s20);
            float nsB1 = fmaf(bs1, c21,  bc1 * s21);
            float ncB1 = fmaf(bc1, c21, -bs1 * s21);
            as0 = nsA0; ac0 = ncA0; as1 = nsA1; ac1 = ncA1;
            bs0 = nsB0; bc0 = ncB0; bs1 = nsB1; bc1 = ncB1;
        }
    }
}

extern "C" void kernel_launch(void* const* d_in, const int* in_sizes, int n_in,
                              void* d_out, int out_size) {
    (void)d_in; (void)in_sizes; (void)n_in;
    const int seq_len = out_size / D_MODEL;    // 8192
    float4* out = (float4*)d_out;

    const int grid = (seq_len + ROWS_PER_BLOCK - 1) / ROWS_PER_BLOCK;  // 2048
    pe_kernel<<<grid, THREADS>>>(out, seq_len);
}